// round 1
// baseline (speedup 1.0000x reference)
#include <cuda_runtime.h>
#include <math.h>

#define BATCH 256
#define TLEN  256
#define HID   256
#define G3    768   // 3*H

// Scratch (device globals — no allocation)
__device__ float g_gx0[BATCH * TLEN * G3];   // layer0 precomputed gi x-part (+b_ih)
__device__ float g_gx1[BATCH * TLEN * G3];   // layer1
__device__ float g_h0[2][BATCH * HID];       // double-buffered hidden state, parity = t&1
__device__ float g_h1[2][BATCH * HID];

// ---------------------------------------------------------------------------
// init: copy initial hidden states into both parity buffers
// ---------------------------------------------------------------------------
__global__ void init_state(const float* __restrict__ hx0, const float* __restrict__ hx1) {
    int i = blockIdx.x * blockDim.x + threadIdx.x;
    if (i < BATCH * HID) {
        g_h0[0][i] = hx0[i];
        g_h0[1][i] = hx0[i];
        g_h1[0][i] = hx1[i];
        g_h1[1][i] = hx1[i];
    }
}

// ---------------------------------------------------------------------------
// Precompute: gx[m][j] = mask[m] * sum_k x[m][k]*W[j][k] + b_ih[j]
//   m = b*T + t,  j in [0,768),  K = 256 (x-part columns of W_ih, row stride 512)
//   layer0 mask: dx_layer_zero[b][t];  layer1 mask: dx[b][0][t]
// CTA tile 128(m) x 64(j), K-chunks of 16, 256 threads, 8x4 microtile.
// ---------------------------------------------------------------------------
__global__ __launch_bounds__(256) void precompute_kernel(
    const float* __restrict__ x, const float* __restrict__ W,
    const float* __restrict__ bias,
    const int* __restrict__ dx, const int* __restrict__ dxlz, int layer)
{
    __shared__ float As[16][128];
    __shared__ float Bs[16][64];

    float* gx = layer ? g_gx1 : g_gx0;
    int mBase = blockIdx.x * 128;
    int jBase = blockIdx.y * 64;
    int tid = threadIdx.x;
    int tmi = tid & 15;     // m subtile index (x8)
    int tji = tid >> 4;     // j subtile index (x4)

    float acc[8][4];
#pragma unroll
    for (int i = 0; i < 8; i++)
#pragma unroll
        for (int j = 0; j < 4; j++) acc[i][j] = 0.0f;

    for (int kk = 0; kk < 256; kk += 16) {
        __syncthreads();
        // stage A (x rows, masked), transposed to [k][m]
#pragma unroll
        for (int i = 0; i < 2; i++) {
            int idx = tid + i * 256;     // 0..511 float4s
            int m   = idx & 127;
            int k4  = idx >> 7;          // 0..3
            int mg  = mBase + m;
            float msk;
            if (layer == 0) msk = (float)dxlz[mg];
            else            msk = (float)dx[((mg >> 8) << 9) + (mg & 255)];
            float4 v = *(const float4*)(x + (size_t)mg * 256 + kk + k4 * 4);
            As[k4 * 4 + 0][m] = v.x * msk;
            As[k4 * 4 + 1][m] = v.y * msk;
            As[k4 * 4 + 2][m] = v.z * msk;
            As[k4 * 4 + 3][m] = v.w * msk;
        }
        // stage B (W_ih rows, x-part cols), transposed to [k][j]
        {
            int j  = tid & 63;
            int k4 = tid >> 6;   // 0..3
            float4 v = *(const float4*)(W + (size_t)(jBase + j) * 512 + kk + k4 * 4);
            Bs[k4 * 4 + 0][j] = v.x;
            Bs[k4 * 4 + 1][j] = v.y;
            Bs[k4 * 4 + 2][j] = v.z;
            Bs[k4 * 4 + 3][j] = v.w;
        }
        __syncthreads();
#pragma unroll
        for (int k = 0; k < 16; k++) {
            float4 a0 = *(const float4*)&As[k][tmi * 8];
            float4 a1 = *(const float4*)&As[k][tmi * 8 + 4];
            float4 bv = *(const float4*)&Bs[k][tji * 4];
            float am[8] = {a0.x, a0.y, a0.z, a0.w, a1.x, a1.y, a1.z, a1.w};
            float bm[4] = {bv.x, bv.y, bv.z, bv.w};
#pragma unroll
            for (int i = 0; i < 8; i++)
#pragma unroll
                for (int j = 0; j < 4; j++) acc[i][j] += am[i] * bm[j];
        }
    }

    float4 bb = *(const float4*)(bias + jBase + tji * 4);
#pragma unroll
    for (int i = 0; i < 8; i++) {
        int m = mBase + tmi * 8 + i;
        float4 o;
        o.x = acc[i][0] + bb.x;
        o.y = acc[i][1] + bb.y;
        o.z = acc[i][2] + bb.z;
        o.w = acc[i][3] + bb.w;
        *(float4*)(gx + (size_t)m * G3 + jBase + tji * 4) = o;
    }
}

// ---------------------------------------------------------------------------
// Step kernel: one layer of one timestep.
//   accI[j] = dot(hA[b], Wih[j][256:])     (scaled by mA[b] afterwards)
//   accH[j] = dot(hB[b], Whh[j])           (scaled by fB[b] afterwards)
//   gi = gx[b,t,j] + mA*accI ; gh = b_hh[j] + fB*accH
//   r=sig, z=sig, n=tanh(giN + r*ghN); hUsed = hB*fB
//   hnew = (1-z)*n + z*hUsed; res = bypass ? hUsed : hnew
// Grid (8,16): CTA tile 32b x 16u (x3 gates). 128 threads, microtile 2b x 2u.
// ---------------------------------------------------------------------------
#define KC 64

__global__ __launch_bounds__(128) void step_kernel(
    int t, int layer,
    const float* __restrict__ Wih, const float* __restrict__ Whh,
    const float* __restrict__ bhh,
    const int* __restrict__ dx, const int* __restrict__ dxlz,
    float* __restrict__ out)
{
    __shared__ float sA[KC][32];          // hA rows, k-major
    __shared__ float sB[KC][32];          // hB rows, k-major
    __shared__ float sWi[3][KC][16];      // Wih h-part rows (u-tile), k-major
    __shared__ float sWh[3][KC][16];      // Whh rows, k-major

    int p  = t & 1;
    int pn = p ^ 1;
    const float* hA   = layer ? g_h0[pn] : g_h1[p];   // layer1 uses freshly written h0
    const float* hB   = layer ? g_h1[p]  : g_h0[p];
    float*       hOut = layer ? g_h1[pn] : g_h0[pn];
    const float* gx   = layer ? g_gx1    : g_gx0;

    int bTile = blockIdx.x * 32;
    int uTile = blockIdx.y * 16;
    int tid = threadIdx.x;
    int tb = tid & 15;    // 16 b-threads (x2 rows)
    int tu = tid >> 4;    // 8 u-threads (x2 cols)

    float accI[2][2][3];
    float accH[2][2][3];
#pragma unroll
    for (int a = 0; a < 2; a++)
#pragma unroll
        for (int b = 0; b < 2; b++)
#pragma unroll
            for (int g = 0; g < 3; g++) { accI[a][b][g] = 0.0f; accH[a][b][g] = 0.0f; }

    for (int kc = 0; kc < 256; kc += KC) {
        __syncthreads();
        // stage h rows (transpose to k-major)
#pragma unroll
        for (int i = 0; i < 4; i++) {
            int idx = tid + i * 128;   // 0..511 float4s
            int bb  = idx & 31;
            int k4  = idx >> 5;        // 0..15
            float4 v = *(const float4*)(hA + (size_t)(bTile + bb) * HID + kc + k4 * 4);
            sA[k4 * 4 + 0][bb] = v.x; sA[k4 * 4 + 1][bb] = v.y;
            sA[k4 * 4 + 2][bb] = v.z; sA[k4 * 4 + 3][bb] = v.w;
            float4 w = *(const float4*)(hB + (size_t)(bTile + bb) * HID + kc + k4 * 4);
            sB[k4 * 4 + 0][bb] = w.x; sB[k4 * 4 + 1][bb] = w.y;
            sB[k4 * 4 + 2][bb] = w.z; sB[k4 * 4 + 3][bb] = w.w;
        }
        // stage weights for the 16-u tile, all 3 gates, both matrices
#pragma unroll
        for (int i = 0; i < 6; i++) {
            int idx = tid + i * 128;       // 0..767 float4s
            int ul  = idx & 15;
            int k4  = (idx >> 4) & 15;
            int g   = idx >> 8;            // 0..2
            int row = g * HID + uTile + ul;
            float4 v = *(const float4*)(Wih + (size_t)row * 512 + 256 + kc + k4 * 4);
            sWi[g][k4 * 4 + 0][ul] = v.x; sWi[g][k4 * 4 + 1][ul] = v.y;
            sWi[g][k4 * 4 + 2][ul] = v.z; sWi[g][k4 * 4 + 3][ul] = v.w;
            float4 w = *(const float4*)(Whh + (size_t)row * HID + kc + k4 * 4);
            sWh[g][k4 * 4 + 0][ul] = w.x; sWh[g][k4 * 4 + 1][ul] = w.y;
            sWh[g][k4 * 4 + 2][ul] = w.z; sWh[g][k4 * 4 + 3][ul] = w.w;
        }
        __syncthreads();
#pragma unroll
        for (int k = 0; k < KC; k++) {
            float2 a  = *(const float2*)&sA[k][tb * 2];
            float2 hb = *(const float2*)&sB[k][tb * 2];
#pragma unroll
            for (int g = 0; g < 3; g++) {
                float2 wi = *(const float2*)&sWi[g][k][tu * 2];
                float2 wh = *(const float2*)&sWh[g][k][tu * 2];
                accI[0][0][g] += a.x * wi.x;
                accI[0][1][g] += a.x * wi.y;
                accI[1][0][g] += a.y * wi.x;
                accI[1][1][g] += a.y * wi.y;
                accH[0][0][g] += hb.x * wh.x;
                accH[0][1][g] += hb.x * wh.y;
                accH[1][0][g] += hb.y * wh.x;
                accH[1][1][g] += hb.y * wh.y;
            }
        }
    }

    // epilogue: masks, gates, bypass, writes
#pragma unroll
    for (int bi = 0; bi < 2; bi++) {
        int b = bTile + tb * 2 + bi;
        float mA, fB; int byp;
        if (layer == 0) {
            int b0  = dxlz[b * TLEN + t];
            int dd0 = (t > 0) ? dx[(b * 2) * TLEN + t - 1] : 0;
            mA = (float)dd0; fB = 1.0f - (float)dd0; byp = (b0 + dd0 == 0);
        } else {
            int b1  = dx[(b * 2) * TLEN + t];
            int dd1 = (t > 0) ? dx[(b * 2 + 1) * TLEN + t - 1] : 0;
            mA = (float)b1; fB = 1.0f - (float)dd1; byp = (b1 + dd1 == 0);
        }
        const float* gxr = gx + (size_t)(b * TLEN + t) * G3;
#pragma unroll
        for (int ui = 0; ui < 2; ui++) {
            int u = uTile + tu * 2 + ui;
            float hprev = hB[b * HID + u];
            float hUsed = hprev * fB;
            float giR = gxr[u]        + mA * accI[bi][ui][0];
            float giZ = gxr[256 + u]  + mA * accI[bi][ui][1];
            float giN = gxr[512 + u]  + mA * accI[bi][ui][2];
            float ghR = bhh[u]        + fB * accH[bi][ui][0];
            float ghZ = bhh[256 + u]  + fB * accH[bi][ui][1];
            float ghN = bhh[512 + u]  + fB * accH[bi][ui][2];
            float r = 1.0f / (1.0f + expf(-(giR + ghR)));
            float z = 1.0f / (1.0f + expf(-(giZ + ghZ)));
            float n = tanhf(giN + r * ghN);
            float hnew = (1.0f - z) * n + z * hUsed;
            float res = byp ? hUsed : hnew;
            hOut[b * HID + u] = res;
            out[(((size_t)layer * BATCH + b) * TLEN + t) * HID + u] = res;
        }
    }
}

// ---------------------------------------------------------------------------
extern "C" void kernel_launch(void* const* d_in, const int* in_sizes, int n_in,
                              void* d_out, int out_size) {
    const float* x0    = (const float*)d_in[0];
    const float* x1    = (const float*)d_in[1];
    const float* hx0   = (const float*)d_in[2];
    const float* hx1   = (const float*)d_in[3];
    const float* W_ih0 = (const float*)d_in[4];
    const float* W_hh0 = (const float*)d_in[5];
    const float* b_ih0 = (const float*)d_in[6];
    const float* b_hh0 = (const float*)d_in[7];
    const float* W_ih1 = (const float*)d_in[8];
    const float* W_hh1 = (const float*)d_in[9];
    const float* b_ih1 = (const float*)d_in[10];
    const float* b_hh1 = (const float*)d_in[11];
    const int*   dx    = (const int*)d_in[12];
    const int*   dxlz  = (const int*)d_in[13];
    float* out = (float*)d_out;

    init_state<<<256, 256>>>(hx0, hx1);

    dim3 pgrid(512, 12);
    precompute_kernel<<<pgrid, 256>>>(x0, W_ih0, b_ih0, dx, dxlz, 0);
    precompute_kernel<<<pgrid, 256>>>(x1, W_ih1, b_ih1, dx, dxlz, 1);

    dim3 sgrid(8, 16);
    for (int t = 0; t < TLEN; t++) {
        step_kernel<<<sgrid, 128>>>(t, 0, W_ih0, W_hh0, b_hh0, dx, dxlz, out);
        step_kernel<<<sgrid, 128>>>(t, 1, W_ih1, W_hh1, b_hh1, dx, dxlz, out);
    }
}

// round 2
// speedup vs baseline: 1.0001x; 1.0001x over previous
#include <cuda_runtime.h>
#include <math.h>

#define BATCH 256
#define TLEN  256
#define HID   256
#define G3    768   // 3*H

// Scratch (device globals — no allocation)
__device__ float g_gx0[BATCH * TLEN * G3];   // layer0 precomputed gi x-part (+b_ih)
__device__ float g_gx1[BATCH * TLEN * G3];   // layer1
__device__ float g_h0[2][BATCH * HID];       // double-buffered hidden state, parity = t&1
__device__ float g_h1[2][BATCH * HID];

// ---------------------------------------------------------------------------
// init: copy initial hidden states into both parity buffers
// ---------------------------------------------------------------------------
__global__ void init_state(const float* __restrict__ hx0, const float* __restrict__ hx1) {
    int i = blockIdx.x * blockDim.x + threadIdx.x;
    if (i < BATCH * HID) {
        g_h0[0][i] = hx0[i];
        g_h0[1][i] = hx0[i];
        g_h1[0][i] = hx1[i];
        g_h1[1][i] = hx1[i];
    }
}

// ---------------------------------------------------------------------------
// Precompute: gx[m][j] = mask[m] * sum_k x[m][k]*W[j][k] + b_ih[j]
//   m = b*T + t,  j in [0,768),  K = 256 (x-part columns of W_ih, row stride 512)
//   layer0 mask: dx_layer_zero[b][t];  layer1 mask: dx[b][0][t]
// CTA tile 128(m) x 64(j), K-chunks of 16, 256 threads, 8x4 microtile.
// ---------------------------------------------------------------------------
__global__ __launch_bounds__(256) void precompute_kernel(
    const float* __restrict__ x, const float* __restrict__ W,
    const float* __restrict__ bias,
    const int* __restrict__ dx, const int* __restrict__ dxlz, int layer)
{
    __shared__ float As[16][128];
    __shared__ float Bs[16][64];

    float* gx = layer ? g_gx1 : g_gx0;
    int mBase = blockIdx.x * 128;
    int jBase = blockIdx.y * 64;
    int tid = threadIdx.x;
    int tmi = tid & 15;     // m subtile index (x8)
    int tji = tid >> 4;     // j subtile index (x4)

    float acc[8][4];
#pragma unroll
    for (int i = 0; i < 8; i++)
#pragma unroll
        for (int j = 0; j < 4; j++) acc[i][j] = 0.0f;

    for (int kk = 0; kk < 256; kk += 16) {
        __syncthreads();
        // stage A (x rows, masked), transposed to [k][m]
#pragma unroll
        for (int i = 0; i < 2; i++) {
            int idx = tid + i * 256;     // 0..511 float4s
            int m   = idx & 127;
            int k4  = idx >> 7;          // 0..3
            int mg  = mBase + m;
            float msk;
            if (layer == 0) msk = (float)dxlz[mg];
            else            msk = (float)dx[((mg >> 8) << 9) + (mg & 255)];
            float4 v = *(const float4*)(x + (size_t)mg * 256 + kk + k4 * 4);
            As[k4 * 4 + 0][m] = v.x * msk;
            As[k4 * 4 + 1][m] = v.y * msk;
            As[k4 * 4 + 2][m] = v.z * msk;
            As[k4 * 4 + 3][m] = v.w * msk;
        }
        // stage B (W_ih rows, x-part cols), transposed to [k][j]
        {
            int j  = tid & 63;
            int k4 = tid >> 6;   // 0..3
            float4 v = *(const float4*)(W + (size_t)(jBase + j) * 512 + kk + k4 * 4);
            Bs[k4 * 4 + 0][j] = v.x;
            Bs[k4 * 4 + 1][j] = v.y;
            Bs[k4 * 4 + 2][j] = v.z;
            Bs[k4 * 4 + 3][j] = v.w;
        }
        __syncthreads();
#pragma unroll
        for (int k = 0; k < 16; k++) {
            float4 a0 = *(const float4*)&As[k][tmi * 8];
            float4 a1 = *(const float4*)&As[k][tmi * 8 + 4];
            float4 bv = *(const float4*)&Bs[k][tji * 4];
            float am[8] = {a0.x, a0.y, a0.z, a0.w, a1.x, a1.y, a1.z, a1.w};
            float bm[4] = {bv.x, bv.y, bv.z, bv.w};
#pragma unroll
            for (int i = 0; i < 8; i++)
#pragma unroll
                for (int j = 0; j < 4; j++) acc[i][j] += am[i] * bm[j];
        }
    }

    float4 bb = *(const float4*)(bias + jBase + tji * 4);
#pragma unroll
    for (int i = 0; i < 8; i++) {
        int m = mBase + tmi * 8 + i;
        float4 o;
        o.x = acc[i][0] + bb.x;
        o.y = acc[i][1] + bb.y;
        o.z = acc[i][2] + bb.z;
        o.w = acc[i][3] + bb.w;
        *(float4*)(gx + (size_t)m * G3 + jBase + tji * 4) = o;
    }
}

// ---------------------------------------------------------------------------
// Step kernel: one layer of one timestep.
//   accI[j] = dot(hA[b], Wih[j][256:])     (scaled by mA[b] afterwards)
//   accH[j] = dot(hB[b], Whh[j])           (scaled by fB[b] afterwards)
//   gi = gx[b,t,j] + mA*accI ; gh = b_hh[j] + fB*accH
//   r=sig, z=sig, n=tanh(giN + r*ghN); hUsed = hB*fB
//   hnew = (1-z)*n + z*hUsed; res = bypass ? hUsed : hnew
// Grid (8,16): CTA tile 32b x 16u (x3 gates). 128 threads, microtile 2b x 2u.
// ---------------------------------------------------------------------------
#define KC 64

__global__ __launch_bounds__(128) void step_kernel(
    int t, int layer,
    const float* __restrict__ Wih, const float* __restrict__ Whh,
    const float* __restrict__ bhh,
    const int* __restrict__ dx, const int* __restrict__ dxlz,
    float* __restrict__ out)
{
    __shared__ float sA[KC][32];          // hA rows, k-major
    __shared__ float sB[KC][32];          // hB rows, k-major
    __shared__ float sWi[3][KC][16];      // Wih h-part rows (u-tile), k-major
    __shared__ float sWh[3][KC][16];      // Whh rows, k-major

    int p  = t & 1;
    int pn = p ^ 1;
    const float* hA   = layer ? g_h0[pn] : g_h1[p];   // layer1 uses freshly written h0
    const float* hB   = layer ? g_h1[p]  : g_h0[p];
    float*       hOut = layer ? g_h1[pn] : g_h0[pn];
    const float* gx   = layer ? g_gx1    : g_gx0;

    int bTile = blockIdx.x * 32;
    int uTile = blockIdx.y * 16;
    int tid = threadIdx.x;
    int tb = tid & 15;    // 16 b-threads (x2 rows)
    int tu = tid >> 4;    // 8 u-threads (x2 cols)

    float accI[2][2][3];
    float accH[2][2][3];
#pragma unroll
    for (int a = 0; a < 2; a++)
#pragma unroll
        for (int b = 0; b < 2; b++)
#pragma unroll
            for (int g = 0; g < 3; g++) { accI[a][b][g] = 0.0f; accH[a][b][g] = 0.0f; }

    for (int kc = 0; kc < 256; kc += KC) {
        __syncthreads();
        // stage h rows (transpose to k-major)
#pragma unroll
        for (int i = 0; i < 4; i++) {
            int idx = tid + i * 128;   // 0..511 float4s
            int bb  = idx & 31;
            int k4  = idx >> 5;        // 0..15
            float4 v = *(const float4*)(hA + (size_t)(bTile + bb) * HID + kc + k4 * 4);
            sA[k4 * 4 + 0][bb] = v.x; sA[k4 * 4 + 1][bb] = v.y;
            sA[k4 * 4 + 2][bb] = v.z; sA[k4 * 4 + 3][bb] = v.w;
            float4 w = *(const float4*)(hB + (size_t)(bTile + bb) * HID + kc + k4 * 4);
            sB[k4 * 4 + 0][bb] = w.x; sB[k4 * 4 + 1][bb] = w.y;
            sB[k4 * 4 + 2][bb] = w.z; sB[k4 * 4 + 3][bb] = w.w;
        }
        // stage weights for the 16-u tile, all 3 gates, both matrices
#pragma unroll
        for (int i = 0; i < 6; i++) {
            int idx = tid + i * 128;       // 0..767 float4s
            int ul  = idx & 15;
            int k4  = (idx >> 4) & 15;
            int g   = idx >> 8;            // 0..2
            int row = g * HID + uTile + ul;
            float4 v = *(const float4*)(Wih + (size_t)row * 512 + 256 + kc + k4 * 4);
            sWi[g][k4 * 4 + 0][ul] = v.x; sWi[g][k4 * 4 + 1][ul] = v.y;
            sWi[g][k4 * 4 + 2][ul] = v.z; sWi[g][k4 * 4 + 3][ul] = v.w;
            float4 w = *(const float4*)(Whh + (size_t)row * HID + kc + k4 * 4);
            sWh[g][k4 * 4 + 0][ul] = w.x; sWh[g][k4 * 4 + 1][ul] = w.y;
            sWh[g][k4 * 4 + 2][ul] = w.z; sWh[g][k4 * 4 + 3][ul] = w.w;
        }
        __syncthreads();
#pragma unroll
        for (int k = 0; k < KC; k++) {
            float2 a  = *(const float2*)&sA[k][tb * 2];
            float2 hb = *(const float2*)&sB[k][tb * 2];
#pragma unroll
            for (int g = 0; g < 3; g++) {
                float2 wi = *(const float2*)&sWi[g][k][tu * 2];
                float2 wh = *(const float2*)&sWh[g][k][tu * 2];
                accI[0][0][g] += a.x * wi.x;
                accI[0][1][g] += a.x * wi.y;
                accI[1][0][g] += a.y * wi.x;
                accI[1][1][g] += a.y * wi.y;
                accH[0][0][g] += hb.x * wh.x;
                accH[0][1][g] += hb.x * wh.y;
                accH[1][0][g] += hb.y * wh.x;
                accH[1][1][g] += hb.y * wh.y;
            }
        }
    }

    // epilogue: masks, gates, bypass, writes
#pragma unroll
    for (int bi = 0; bi < 2; bi++) {
        int b = bTile + tb * 2 + bi;
        float mA, fB; int byp;
        if (layer == 0) {
            int b0  = dxlz[b * TLEN + t];
            int dd0 = (t > 0) ? dx[(b * 2) * TLEN + t - 1] : 0;
            mA = (float)dd0; fB = 1.0f - (float)dd0; byp = (b0 + dd0 == 0);
        } else {
            int b1  = dx[(b * 2) * TLEN + t];
            int dd1 = (t > 0) ? dx[(b * 2 + 1) * TLEN + t - 1] : 0;
            mA = (float)b1; fB = 1.0f - (float)dd1; byp = (b1 + dd1 == 0);
        }
        const float* gxr = gx + (size_t)(b * TLEN + t) * G3;
#pragma unroll
        for (int ui = 0; ui < 2; ui++) {
            int u = uTile + tu * 2 + ui;
            float hprev = hB[b * HID + u];
            float hUsed = hprev * fB;
            float giR = gxr[u]        + mA * accI[bi][ui][0];
            float giZ = gxr[256 + u]  + mA * accI[bi][ui][1];
            float giN = gxr[512 + u]  + mA * accI[bi][ui][2];
            float ghR = bhh[u]        + fB * accH[bi][ui][0];
            float ghZ = bhh[256 + u]  + fB * accH[bi][ui][1];
            float ghN = bhh[512 + u]  + fB * accH[bi][ui][2];
            float r = 1.0f / (1.0f + expf(-(giR + ghR)));
            float z = 1.0f / (1.0f + expf(-(giZ + ghZ)));
            float n = tanhf(giN + r * ghN);
            float hnew = (1.0f - z) * n + z * hUsed;
            float res = byp ? hUsed : hnew;
            hOut[b * HID + u] = res;
            out[(((size_t)layer * BATCH + b) * TLEN + t) * HID + u] = res;
        }
    }
}

// ---------------------------------------------------------------------------
extern "C" void kernel_launch(void* const* d_in, const int* in_sizes, int n_in,
                              void* d_out, int out_size) {
    const float* x0    = (const float*)d_in[0];
    const float* x1    = (const float*)d_in[1];
    const float* hx0   = (const float*)d_in[2];
    const float* hx1   = (const float*)d_in[3];
    const float* W_ih0 = (const float*)d_in[4];
    const float* W_hh0 = (const float*)d_in[5];
    const float* b_ih0 = (const float*)d_in[6];
    const float* b_hh0 = (const float*)d_in[7];
    const float* W_ih1 = (const float*)d_in[8];
    const float* W_hh1 = (const float*)d_in[9];
    const float* b_ih1 = (const float*)d_in[10];
    const float* b_hh1 = (const float*)d_in[11];
    const int*   dx    = (const int*)d_in[12];
    const int*   dxlz  = (const int*)d_in[13];
    float* out = (float*)d_out;

    init_state<<<256, 256>>>(hx0, hx1);

    dim3 pgrid(512, 12);
    precompute_kernel<<<pgrid, 256>>>(x0, W_ih0, b_ih0, dx, dxlz, 0);
    precompute_kernel<<<pgrid, 256>>>(x1, W_ih1, b_ih1, dx, dxlz, 1);

    dim3 sgrid(8, 16);
    for (int t = 0; t < TLEN; t++) {
        step_kernel<<<sgrid, 128>>>(t, 0, W_ih0, W_hh0, b_hh0, dx, dxlz, out);
        step_kernel<<<sgrid, 128>>>(t, 1, W_ih1, W_hh1, b_hh1, dx, dxlz, out);
    }
}